// round 10
// baseline (speedup 1.0000x reference)
#include <cuda_runtime.h>
#include <cstddef>

// CRF NLL: emissions (B,S,T) f32, tags (B,S) int32-staged, mask (B,S) f32,
// transitions (T,T) f32, start_transitions (T) f32, end_transitions (T) f32
// out: scalar f32 = sum_b (partition_b - score_b)
#define B_SZ 512
#define S_SZ 1024
#define T_SZ 32
#define FULL 0xFFFFFFFFu
#define LN2F 0.69314718055994530942f

typedef unsigned long long ull;

__device__ float    g_res[B_SZ];
__device__ unsigned g_cnt;   // zero-init; reset by last block each launch

// ---- packed f32x2 helpers (Blackwell FFMA2/FADD2 — PTX-only, ptxas won't fuse) ----
__device__ __forceinline__ ull ffma2(ull a, ull b, ull c) {
    ull d; asm("fma.rn.f32x2 %0, %1, %2, %3;" : "=l"(d) : "l"(a), "l"(b), "l"(c));
    return d;
}
__device__ __forceinline__ ull fadd2(ull a, ull b) {
    ull d; asm("add.rn.f32x2 %0, %1, %2;" : "=l"(d) : "l"(a), "l"(b));
    return d;
}
__device__ __forceinline__ ull pack2(float lo, float hi) {
    ull d; asm("mov.b64 %0, {%1, %2};" : "=l"(d)
               : "r"(__float_as_uint(lo)), "r"(__float_as_uint(hi)));
    return d;
}
__device__ __forceinline__ float hadd2(ull v) {
    unsigned lo, hi;
    asm("mov.b64 {%0, %1}, %2;" : "=r"(lo), "=r"(hi) : "l"(v));
    return __uint_as_float(lo) + __uint_as_float(hi);
}

// 2^-floor(log2(max over warp of w)) as (scale, exponent k), exact power of 2
__device__ __forceinline__ void scale_from_max(float w, float& sc, int& k)
{
    float mx = w;
#pragma unroll
    for (int o = 16; o > 0; o >>= 1)
        mx = fmaxf(mx, __shfl_xor_sync(FULL, mx, o));
    const int e = (int)((__float_as_uint(mx) >> 23) & 0xFF);
    sc = __uint_as_float((unsigned)(254 - e) << 23);   // 2^(127-e)
    k  = e - 127;
}

// One step for both batches, f32x2 dot. u = ring slot (compile-time 0..7),
// read parity u&1, write parity (u+1)&1. RENORM applies the scale computed
// 4 steps earlier, then launches the next scale computation (lag pipeline).
#define STEP(u, PREFETCH, RENORM, s_)                                          \
    {                                                                          \
        const float e0 = ee0[u], e1 = ee1[u];                                  \
        const float mA = mk0[u], mB = mk1[u];                                  \
        if (PREFETCH) {                                                        \
            ee0[u] = __expf(__ldg(emb0 + (size_t)((s_) + 8) * T_SZ + lane));   \
            ee1[u] = __expf(__ldg(emb1 + (size_t)((s_) + 8) * T_SZ + lane));   \
            mk0[u] = __ldg(mb0 + ((s_) + 8));                                  \
            mk1[u] = __ldg(mb1 + ((s_) + 8));                                  \
        }                                                                      \
        __syncwarp();                                                          \
        const ulonglong2* rp0 = ((u) & 1) ? rd0b : rd0a;                       \
        const ulonglong2* rp1 = ((u) & 1) ? rd1b : rd1a;                       \
        ull p0 = 0, p1 = 0, p2 = 0, p3 = 0;                                    \
        ull q0 = 0, q1 = 0, q2 = 0, q3 = 0;                                    \
        _Pragma("unroll")                                                      \
        for (int c = 0; c < 8; ++c) {                                          \
            const ulonglong2 W0 = rp0[c];                                      \
            const ulonglong2 W1 = rp1[c];                                      \
            if ((c & 1) == 0) {                                                \
                p0 = ffma2(W0.x, et2[2*c],   p0);                              \
                p1 = ffma2(W0.y, et2[2*c+1], p1);                              \
                q0 = ffma2(W1.x, et2[2*c],   q0);                              \
                q1 = ffma2(W1.y, et2[2*c+1], q1);                              \
            } else {                                                           \
                p2 = ffma2(W0.x, et2[2*c],   p2);                              \
                p3 = ffma2(W0.y, et2[2*c+1], p3);                              \
                q2 = ffma2(W1.x, et2[2*c],   q2);                              \
                q3 = ffma2(W1.y, et2[2*c+1], q3);                              \
            }                                                                  \
        }                                                                      \
        const float dot0 = hadd2(fadd2(fadd2(p0, p2), fadd2(p1, p3)));         \
        const float dot1 = hadd2(fadd2(fadd2(q0, q2), fadd2(q1, q3)));         \
        const float wn0 = dot0 * e0;                                           \
        const float wn1 = dot1 * e1;                                           \
        w0 = fmaf(mA, wn0 - w0, w0);                                           \
        w1 = fmaf(mB, wn1 - w1, w1);                                           \
        if (RENORM) { w0 *= sc0; E0 += k0; w1 *= sc1; E1 += k1; }              \
        sw[((u)+1)&1][widx][0][lane] = w0;                                     \
        sw[((u)+1)&1][widx][1][lane] = w1;                                     \
        if (RENORM) { scale_from_max(w0, sc0, k0); scale_from_max(w1, sc1, k1); } \
    }

__global__ void __launch_bounds__(64) crf_kernel(
    const float* __restrict__ em,
    const int*   __restrict__ tags,
    const float* __restrict__ mask,
    const float* __restrict__ trans,
    const float* __restrict__ startT,
    const float* __restrict__ endT,
    float*       __restrict__ out)
{
    const int widx = threadIdx.x >> 5;          // 0..1
    const int lane = threadIdx.x & 31;
    const int wg   = blockIdx.x * 2 + widx;     // 128 blocks x 2 warps = 256 warps
    const int b0   = wg * 2;                    // 2 batches per warp
    const int b1   = b0 + 1;

    __shared__ __align__(16) float sw[2][2][2][32];  // [parity][warp][batch][lane]
    __shared__ float red[64];
    __shared__ unsigned s_ticket;

    // et2[k] = packed pair (exp(trans[2k? ...]) along i for column 'lane':
    // et2[k] holds (expT[2k][lane], expT[2k+1][lane])
    ull et2[T_SZ / 2];
#pragma unroll
    for (int k = 0; k < T_SZ / 2; ++k) {
        const float a = __expf(__ldg(trans + (2 * k)     * T_SZ + lane));
        const float b = __expf(__ldg(trans + (2 * k + 1) * T_SZ + lane));
        et2[k] = pack2(a, b);
    }

    const float* emb0 = em + (size_t)b0 * S_SZ * T_SZ;
    const float* emb1 = em + (size_t)b1 * S_SZ * T_SZ;
    const float* mb0  = mask + (size_t)b0 * S_SZ;
    const float* mb1  = mask + (size_t)b1 * S_SZ;

    // exp-domain state: alpha_j = log(w_j) + E*ln2
    const float stv = __ldg(startT + lane);
    float w0 = __expf(stv + __ldg(emb0 + lane));
    float w1 = __expf(stv + __ldg(emb1 + lane));
    int E0 = 0, E1 = 0;

    sw[0][widx][0][lane] = w0;
    sw[0][widx][1][lane] = w1;

    // pending renorm scale (applied 4 steps from now)
    float sc0, sc1; int k0, k1;
    scale_from_max(w0, sc0, k0);
    scale_from_max(w1, sc1, k1);

    // depth-8 prefetch ring: exp(emission) computed 8 steps ahead of use
    float ee0[8], ee1[8], mk0[8], mk1[8];
#pragma unroll
    for (int k = 0; k < 8; ++k) {
        ee0[k] = __expf(__ldg(emb0 + (1 + k) * T_SZ + lane));
        ee1[k] = __expf(__ldg(emb1 + (1 + k) * T_SZ + lane));
        mk0[k] = __ldg(mb0 + 1 + k);
        mk1[k] = __ldg(mb1 + 1 + k);
    }

    const ulonglong2* rd0a = (const ulonglong2*)sw[0][widx][0];
    const ulonglong2* rd0b = (const ulonglong2*)sw[1][widx][0];
    const ulonglong2* rd1a = (const ulonglong2*)sw[0][widx][1];
    const ulonglong2* rd1b = (const ulonglong2*)sw[1][widx][1];

    // main loop: steps 1..1016 as 127 groups of 8 (compile-time slots/parity)
    for (int g = 0; g < 127; ++g) {
        const int sb = 1 + g * 8;
        const bool pfl = (g < 126);   // last group: slot 7 would fetch s=1024
        STEP(0, true, false, sb + 0)
        STEP(1, true, false, sb + 1)
        STEP(2, true, false, sb + 2)
        STEP(3, true, true,  sb + 3)
        STEP(4, true, false, sb + 4)
        STEP(5, true, false, sb + 5)
        STEP(6, true, false, sb + 6)
        STEP(7, pfl,  true,  sb + 7)
    }
    // tail: steps 1017..1023 (slots 0..6), no prefetch, one renorm mid-tail
    STEP(0, false, false, 1017)
    STEP(1, false, false, 1018)
    STEP(2, false, false, 1019)
    STEP(3, false, true,  1020)
    STEP(4, false, false, 1021)
    STEP(5, false, false, 1022)
    STEP(6, false, false, 1023)

    // ---- partition = E*ln2 + log( sum_j w_j * exp(endT_j) ) ----
    const float ve = __expf(__ldg(endT + lane));
    float v0 = w0 * ve;
    float v1 = w1 * ve;
#pragma unroll
    for (int o = 16; o > 0; o >>= 1) {
        v0 += __shfl_xor_sync(FULL, v0, o);
        v1 += __shfl_xor_sync(FULL, v1, o);
    }
    const float part0 = fmaf((float)E0, LN2F, __logf(v0));
    const float part1 = fmaf((float)E1, LN2F, __logf(v1));

    // ---- scores: lanes stride over positions, both batches interleaved ----
    const int* tb0 = tags + (size_t)b0 * S_SZ;
    const int* tb1 = tags + (size_t)b1 * S_SZ;
    float sa0 = 0.f, sa1 = 0.f, ms0 = 0.f, ms1 = 0.f;
#pragma unroll 4
    for (int s = lane; s < S_SZ; s += 32) {
        const float mA = __ldg(mb0 + s);
        const float mB = __ldg(mb1 + s);
        ms0 += mA; ms1 += mB;
        if (s == 0) {
            const int tA = __ldg(tb0) & (T_SZ - 1);
            const int tB = __ldg(tb1) & (T_SZ - 1);
            sa0 += __ldg(startT + tA) + __ldg(emb0 + tA);
            sa1 += __ldg(startT + tB) + __ldg(emb1 + tB);
        } else {
            const int cA = __ldg(tb0 + s)     & (T_SZ - 1);
            const int pA = __ldg(tb0 + s - 1) & (T_SZ - 1);
            const int cB = __ldg(tb1 + s)     & (T_SZ - 1);
            const int pB = __ldg(tb1 + s - 1) & (T_SZ - 1);
            sa0 += (__ldg(emb0 + s * T_SZ + cA) + __ldg(trans + pA * T_SZ + cA)) * mA;
            sa1 += (__ldg(emb1 + s * T_SZ + cB) + __ldg(trans + pB * T_SZ + cB)) * mB;
        }
    }
#pragma unroll
    for (int o = 16; o > 0; o >>= 1) {
        sa0 += __shfl_xor_sync(FULL, sa0, o);
        sa1 += __shfl_xor_sync(FULL, sa1, o);
        ms0 += __shfl_xor_sync(FULL, ms0, o);
        ms1 += __shfl_xor_sync(FULL, ms1, o);
    }

    if (lane == 0) {
        int l0 = (int)ms0 - 1; l0 = l0 < 0 ? 0 : (l0 >= S_SZ ? S_SZ - 1 : l0);
        int l1 = (int)ms1 - 1; l1 = l1 < 0 ? 0 : (l1 >= S_SZ ? S_SZ - 1 : l1);
        const int tL0 = __ldg(tb0 + l0) & (T_SZ - 1);
        const int tL1 = __ldg(tb1 + l1) & (T_SZ - 1);
        g_res[b0] = part0 - (sa0 + __ldg(endT + tL0));
        g_res[b1] = part1 - (sa1 + __ldg(endT + tL1));
    }

    // ---- fused final reduction: last block to finish sums all 512 ----
    __syncthreads();
    __threadfence();
    if (threadIdx.x == 0)
        s_ticket = atomicAdd(&g_cnt, 1u);
    __syncthreads();

    if (s_ticket == gridDim.x - 1) {
        const int t = threadIdx.x;
        float acc = 0.f;
#pragma unroll
        for (int r = 0; r < 8; ++r)
            acc += g_res[t + 64 * r];
        red[t] = acc;
        __syncthreads();
#pragma unroll
        for (int st = 32; st > 0; st >>= 1) {
            if (t < st) red[t] += red[t + st];
            __syncthreads();
        }
        if (t == 0) { out[0] = red[0]; g_cnt = 0; }
    }
}

extern "C" void kernel_launch(void* const* d_in, const int* in_sizes, int n_in,
                              void* d_out, int out_size)
{
    const float* em     = (const float*)d_in[0];
    const int*   tags   = (const int*)d_in[1];
    const float* mask   = (const float*)d_in[2];
    const float* trans  = (const float*)d_in[3];
    const float* startT = (const float*)d_in[4];
    const float* endT   = (const float*)d_in[5];
    float* out = (float*)d_out;

    (void)in_sizes; (void)n_in; (void)out_size;

    // 128 blocks x 64 threads = 256 warps, 2 batches per warp
    crf_kernel<<<128, 64>>>(em, tags, mask, trans, startT, endT, out);
}

// round 11
// speedup vs baseline: 1.0035x; 1.0035x over previous
#include <cuda_runtime.h>
#include <cstddef>

// CRF NLL: emissions (B,S,T) f32, tags (B,S) int32-staged, mask (B,S) f32,
// transitions (T,T) f32, start_transitions (T) f32, end_transitions (T) f32
// out: scalar f32 = sum_b (partition_b - score_b)
#define B_SZ 512
#define S_SZ 1024
#define T_SZ 32
#define FULL 0xFFFFFFFFu
#define LN2F 0.69314718055994530942f

typedef unsigned long long ull;

__device__ float    g_res[B_SZ];
__device__ unsigned g_cnt;   // zero-init; reset by last block each launch

// ---- packed f32x2 helpers (Blackwell FFMA2/FADD2 — PTX-only, ptxas won't fuse) ----
__device__ __forceinline__ ull ffma2(ull a, ull b, ull c) {
    ull d; asm("fma.rn.f32x2 %0, %1, %2, %3;" : "=l"(d) : "l"(a), "l"(b), "l"(c));
    return d;
}
__device__ __forceinline__ ull fadd2(ull a, ull b) {
    ull d; asm("add.rn.f32x2 %0, %1, %2;" : "=l"(d) : "l"(a), "l"(b));
    return d;
}
__device__ __forceinline__ ull pack2(float lo, float hi) {
    ull d; asm("mov.b64 %0, {%1, %2};" : "=l"(d)
               : "r"(__float_as_uint(lo)), "r"(__float_as_uint(hi)));
    return d;
}
__device__ __forceinline__ float hadd2(ull v) {
    unsigned lo, hi;
    asm("mov.b64 {%0, %1}, %2;" : "=r"(lo), "=r"(hi) : "l"(v));
    return __uint_as_float(lo) + __uint_as_float(hi);
}

// 2^-floor(log2(max over warp of w)) as (scale, exponent k), exact power of 2
__device__ __forceinline__ void scale_from_max(float w, float& sc, int& k)
{
    float mx = w;
#pragma unroll
    for (int o = 16; o > 0; o >>= 1)
        mx = fmaxf(mx, __shfl_xor_sync(FULL, mx, o));
    const int e = (int)((__float_as_uint(mx) >> 23) & 0xFF);
    sc = __uint_as_float((unsigned)(254 - e) << 23);   // 2^(127-e)
    k  = e - 127;
}

// One step for both batches, f32x2 dot. u = ring slot (compile-time 0..7),
// read parity u&1, write parity (u+1)&1. RENORM applies the scale computed
// 4 steps earlier, then launches the next scale computation (lag pipeline).
#define STEP(u, PREFETCH, RENORM, s_)                                          \
    {                                                                          \
        const float e0 = ee0[u], e1 = ee1[u];                                  \
        const float mA = mk0[u], mB = mk1[u];                                  \
        if (PREFETCH) {                                                        \
            ee0[u] = __expf(__ldg(emb0 + (size_t)((s_) + 8) * T_SZ + lane));   \
            ee1[u] = __expf(__ldg(emb1 + (size_t)((s_) + 8) * T_SZ + lane));   \
            mk0[u] = __ldg(mb0 + ((s_) + 8));                                  \
            mk1[u] = __ldg(mb1 + ((s_) + 8));                                  \
        }                                                                      \
        __syncwarp();                                                          \
        const ulonglong2* rp0 = ((u) & 1) ? rd0b : rd0a;                       \
        const ulonglong2* rp1 = ((u) & 1) ? rd1b : rd1a;                       \
        ull p0 = 0, p1 = 0, p2 = 0, p3 = 0;                                    \
        ull q0 = 0, q1 = 0, q2 = 0, q3 = 0;                                    \
        _Pragma("unroll")                                                      \
        for (int c = 0; c < 8; ++c) {                                          \
            const ulonglong2 W0 = rp0[c];                                      \
            const ulonglong2 W1 = rp1[c];                                      \
            if ((c & 1) == 0) {                                                \
                p0 = ffma2(W0.x, et2[2*c],   p0);                              \
                p1 = ffma2(W0.y, et2[2*c+1], p1);                              \
                q0 = ffma2(W1.x, et2[2*c],   q0);                              \
                q1 = ffma2(W1.y, et2[2*c+1], q1);                              \
            } else {                                                           \
                p2 = ffma2(W0.x, et2[2*c],   p2);                              \
                p3 = ffma2(W0.y, et2[2*c+1], p3);                              \
                q2 = ffma2(W1.x, et2[2*c],   q2);                              \
                q3 = ffma2(W1.y, et2[2*c+1], q3);                              \
            }                                                                  \
        }                                                                      \
        const float dot0 = hadd2(fadd2(fadd2(p0, p2), fadd2(p1, p3)));         \
        const float dot1 = hadd2(fadd2(fadd2(q0, q2), fadd2(q1, q3)));         \
        const float wn0 = dot0 * e0;                                           \
        const float wn1 = dot1 * e1;                                           \
        w0 = fmaf(mA, wn0 - w0, w0);                                           \
        w1 = fmaf(mB, wn1 - w1, w1);                                           \
        if (RENORM) { w0 *= sc0; E0 += k0; w1 *= sc1; E1 += k1; }              \
        sw[((u)+1)&1][widx][0][lane] = w0;                                     \
        sw[((u)+1)&1][widx][1][lane] = w1;                                     \
        if (RENORM) { scale_from_max(w0, sc0, k0); scale_from_max(w1, sc1, k1); } \
    }

__global__ void __launch_bounds__(64) crf_kernel(
    const float* __restrict__ em,
    const int*   __restrict__ tags,
    const float* __restrict__ mask,
    const float* __restrict__ trans,
    const float* __restrict__ startT,
    const float* __restrict__ endT,
    float*       __restrict__ out)
{
    const int widx = threadIdx.x >> 5;          // 0..1
    const int lane = threadIdx.x & 31;
    const int wg   = blockIdx.x * 2 + widx;     // 128 blocks x 2 warps = 256 warps
    const int b0   = wg * 2;                    // 2 batches per warp
    const int b1   = b0 + 1;

    __shared__ __align__(16) float sw[2][2][2][32];  // [parity][warp][batch][lane]
    __shared__ float red[64];
    __shared__ unsigned s_ticket;

    // et2[k] = packed pair (exp(trans[2k? ...]) along i for column 'lane':
    // et2[k] holds (expT[2k][lane], expT[2k+1][lane])
    ull et2[T_SZ / 2];
#pragma unroll
    for (int k = 0; k < T_SZ / 2; ++k) {
        const float a = __expf(__ldg(trans + (2 * k)     * T_SZ + lane));
        const float b = __expf(__ldg(trans + (2 * k + 1) * T_SZ + lane));
        et2[k] = pack2(a, b);
    }

    const float* emb0 = em + (size_t)b0 * S_SZ * T_SZ;
    const float* emb1 = em + (size_t)b1 * S_SZ * T_SZ;
    const float* mb0  = mask + (size_t)b0 * S_SZ;
    const float* mb1  = mask + (size_t)b1 * S_SZ;

    // exp-domain state: alpha_j = log(w_j) + E*ln2
    const float stv = __ldg(startT + lane);
    float w0 = __expf(stv + __ldg(emb0 + lane));
    float w1 = __expf(stv + __ldg(emb1 + lane));
    int E0 = 0, E1 = 0;

    sw[0][widx][0][lane] = w0;
    sw[0][widx][1][lane] = w1;

    // pending renorm scale (applied 4 steps from now)
    float sc0, sc1; int k0, k1;
    scale_from_max(w0, sc0, k0);
    scale_from_max(w1, sc1, k1);

    // depth-8 prefetch ring: exp(emission) computed 8 steps ahead of use
    float ee0[8], ee1[8], mk0[8], mk1[8];
#pragma unroll
    for (int k = 0; k < 8; ++k) {
        ee0[k] = __expf(__ldg(emb0 + (1 + k) * T_SZ + lane));
        ee1[k] = __expf(__ldg(emb1 + (1 + k) * T_SZ + lane));
        mk0[k] = __ldg(mb0 + 1 + k);
        mk1[k] = __ldg(mb1 + 1 + k);
    }

    const ulonglong2* rd0a = (const ulonglong2*)sw[0][widx][0];
    const ulonglong2* rd0b = (const ulonglong2*)sw[1][widx][0];
    const ulonglong2* rd1a = (const ulonglong2*)sw[0][widx][1];
    const ulonglong2* rd1b = (const ulonglong2*)sw[1][widx][1];

    // main loop: steps 1..1016 as 127 groups of 8 (compile-time slots/parity)
    for (int g = 0; g < 127; ++g) {
        const int sb = 1 + g * 8;
        const bool pfl = (g < 126);   // last group: slot 7 would fetch s=1024
        STEP(0, true, false, sb + 0)
        STEP(1, true, false, sb + 1)
        STEP(2, true, false, sb + 2)
        STEP(3, true, true,  sb + 3)
        STEP(4, true, false, sb + 4)
        STEP(5, true, false, sb + 5)
        STEP(6, true, false, sb + 6)
        STEP(7, pfl,  true,  sb + 7)
    }
    // tail: steps 1017..1023 (slots 0..6), no prefetch, one renorm mid-tail
    STEP(0, false, false, 1017)
    STEP(1, false, false, 1018)
    STEP(2, false, false, 1019)
    STEP(3, false, true,  1020)
    STEP(4, false, false, 1021)
    STEP(5, false, false, 1022)
    STEP(6, false, false, 1023)

    // ---- partition = E*ln2 + log( sum_j w_j * exp(endT_j) ) ----
    const float ve = __expf(__ldg(endT + lane));
    float v0 = w0 * ve;
    float v1 = w1 * ve;
#pragma unroll
    for (int o = 16; o > 0; o >>= 1) {
        v0 += __shfl_xor_sync(FULL, v0, o);
        v1 += __shfl_xor_sync(FULL, v1, o);
    }
    const float part0 = fmaf((float)E0, LN2F, __logf(v0));
    const float part1 = fmaf((float)E1, LN2F, __logf(v1));

    // ---- scores: lanes stride over positions, both batches interleaved ----
    const int* tb0 = tags + (size_t)b0 * S_SZ;
    const int* tb1 = tags + (size_t)b1 * S_SZ;
    float sa0 = 0.f, sa1 = 0.f, ms0 = 0.f, ms1 = 0.f;
#pragma unroll 4
    for (int s = lane; s < S_SZ; s += 32) {
        const float mA = __ldg(mb0 + s);
        const float mB = __ldg(mb1 + s);
        ms0 += mA; ms1 += mB;
        if (s == 0) {
            const int tA = __ldg(tb0) & (T_SZ - 1);
            const int tB = __ldg(tb1) & (T_SZ - 1);
            sa0 += __ldg(startT + tA) + __ldg(emb0 + tA);
            sa1 += __ldg(startT + tB) + __ldg(emb1 + tB);
        } else {
            const int cA = __ldg(tb0 + s)     & (T_SZ - 1);
            const int pA = __ldg(tb0 + s - 1) & (T_SZ - 1);
            const int cB = __ldg(tb1 + s)     & (T_SZ - 1);
            const int pB = __ldg(tb1 + s - 1) & (T_SZ - 1);
            sa0 += (__ldg(emb0 + s * T_SZ + cA) + __ldg(trans + pA * T_SZ + cA)) * mA;
            sa1 += (__ldg(emb1 + s * T_SZ + cB) + __ldg(trans + pB * T_SZ + cB)) * mB;
        }
    }
#pragma unroll
    for (int o = 16; o > 0; o >>= 1) {
        sa0 += __shfl_xor_sync(FULL, sa0, o);
        sa1 += __shfl_xor_sync(FULL, sa1, o);
        ms0 += __shfl_xor_sync(FULL, ms0, o);
        ms1 += __shfl_xor_sync(FULL, ms1, o);
    }

    if (lane == 0) {
        int l0 = (int)ms0 - 1; l0 = l0 < 0 ? 0 : (l0 >= S_SZ ? S_SZ - 1 : l0);
        int l1 = (int)ms1 - 1; l1 = l1 < 0 ? 0 : (l1 >= S_SZ ? S_SZ - 1 : l1);
        const int tL0 = __ldg(tb0 + l0) & (T_SZ - 1);
        const int tL1 = __ldg(tb1 + l1) & (T_SZ - 1);
        g_res[b0] = part0 - (sa0 + __ldg(endT + tL0));
        g_res[b1] = part1 - (sa1 + __ldg(endT + tL1));
    }

    // ---- fused final reduction: last block to finish sums all 512 ----
    __syncthreads();
    __threadfence();
    if (threadIdx.x == 0)
        s_ticket = atomicAdd(&g_cnt, 1u);
    __syncthreads();

    if (s_ticket == gridDim.x - 1) {
        const int t = threadIdx.x;
        float acc = 0.f;
#pragma unroll
        for (int r = 0; r < 8; ++r)
            acc += g_res[t + 64 * r];
        red[t] = acc;
        __syncthreads();
#pragma unroll
        for (int st = 32; st > 0; st >>= 1) {
            if (t < st) red[t] += red[t + st];
            __syncthreads();
        }
        if (t == 0) { out[0] = red[0]; g_cnt = 0; }
    }
}

extern "C" void kernel_launch(void* const* d_in, const int* in_sizes, int n_in,
                              void* d_out, int out_size)
{
    const float* em     = (const float*)d_in[0];
    const int*   tags   = (const int*)d_in[1];
    const float* mask   = (const float*)d_in[2];
    const float* trans  = (const float*)d_in[3];
    const float* startT = (const float*)d_in[4];
    const float* endT   = (const float*)d_in[5];
    float* out = (float*)d_out;

    (void)in_sizes; (void)n_in; (void)out_size;

    // 128 blocks x 64 threads = 256 warps, 2 batches per warp
    crf_kernel<<<128, 64>>>(em, tags, mask, trans, startT, endT, out);
}

// round 12
// speedup vs baseline: 1.2166x; 1.2123x over previous
#include <cuda_runtime.h>
#include <cstddef>

// CRF NLL: emissions (B,S,T) f32, tags (B,S) int32-staged, mask (B,S) f32,
// transitions (T,T) f32, start_transitions (T) f32, end_transitions (T) f32
// out: scalar f32 = sum_b (partition_b - score_b)
#define B_SZ 512
#define S_SZ 1024
#define T_SZ 32
#define FULL 0xFFFFFFFFu
#define LN2F 0.69314718055994530942f

__device__ float    g_res[B_SZ];
__device__ unsigned g_cnt;   // zero-init; reset by last block each launch

// 2^-floor(log2(max over warp of w)) as (scale, exponent k), exact power of 2
__device__ __forceinline__ void scale_from_max(float w, float& sc, int& k)
{
    float mx = w;
#pragma unroll
    for (int o = 16; o > 0; o >>= 1)
        mx = fmaxf(mx, __shfl_xor_sync(FULL, mx, o));
    const int e = (int)((__float_as_uint(mx) >> 23) & 0xFF);
    sc = __uint_as_float((unsigned)(254 - e) << 23);   // 2^(127-e)
    k  = e - 127;
}

// One recursion step, register-only SHFL broadcast, pure exp domain.
// u = prefetch ring slot (compile-time 0..7). RENORM applies the scale
// computed 4 steps earlier, then starts computing the next one (lag pipeline).
#define STEP(u, PREFETCH, RENORM, s_)                                         \
    {                                                                          \
        const float ee = eebuf[u];                                             \
        const float m  = mbuf[u];                                              \
        if (PREFETCH) {                                                        \
            eebuf[u] = __expf(__ldg(emb + (size_t)((s_) + 8) * T_SZ + lane));  \
            mbuf[u]  = __ldg(mb + ((s_) + 8));                                 \
        }                                                                      \
        float a0, a1, a2, a3, a4, a5, a6, a7;                                  \
        a0 = __shfl_sync(FULL, w,  0) * et[0];                                 \
        a1 = __shfl_sync(FULL, w,  4) * et[4];                                 \
        a2 = __shfl_sync(FULL, w,  8) * et[8];                                 \
        a3 = __shfl_sync(FULL, w, 12) * et[12];                                \
        a4 = __shfl_sync(FULL, w, 16) * et[16];                                \
        a5 = __shfl_sync(FULL, w, 20) * et[20];                                \
        a6 = __shfl_sync(FULL, w, 24) * et[24];                                \
        a7 = __shfl_sync(FULL, w, 28) * et[28];                                \
        _Pragma("unroll")                                                      \
        for (int r = 1; r < 4; ++r) {                                          \
            a0 = fmaf(__shfl_sync(FULL, w,  0 + r), et[ 0 + r], a0);           \
            a1 = fmaf(__shfl_sync(FULL, w,  4 + r), et[ 4 + r], a1);           \
            a2 = fmaf(__shfl_sync(FULL, w,  8 + r), et[ 8 + r], a2);           \
            a3 = fmaf(__shfl_sync(FULL, w, 12 + r), et[12 + r], a3);           \
            a4 = fmaf(__shfl_sync(FULL, w, 16 + r), et[16 + r], a4);           \
            a5 = fmaf(__shfl_sync(FULL, w, 20 + r), et[20 + r], a5);           \
            a6 = fmaf(__shfl_sync(FULL, w, 24 + r), et[24 + r], a6);           \
            a7 = fmaf(__shfl_sync(FULL, w, 28 + r), et[28 + r], a7);           \
        }                                                                      \
        const float dot = ((a0 + a1) + (a2 + a3)) + ((a4 + a5) + (a6 + a7));   \
        const float wn  = dot * ee;                                            \
        w = fmaf(m, wn - w, w);     /* mask blend: exact for m in {0,1} */     \
        if (RENORM) {                                                          \
            w *= sc_a;  E += k_a;                                              \
            sc_a = sc_b;  k_a = k_b;                                           \
            scale_from_max(w, sc_b, k_b);                                      \
        }                                                                      \
    }

__global__ void __launch_bounds__(128) crf_kernel(
    const float* __restrict__ em,
    const int*   __restrict__ tags,
    const float* __restrict__ mask,
    const float* __restrict__ trans,
    const float* __restrict__ startT,
    const float* __restrict__ endT,
    float*       __restrict__ out)
{
    const int widx = threadIdx.x >> 5;
    const int lane = threadIdx.x & 31;
    const int b    = blockIdx.x * 4 + widx;   // 128 blocks x 4 warps = 512

    __shared__ float red[128];
    __shared__ unsigned s_ticket;

    // lane j holds column j of exp(transitions): et[i] = expT[i][j]
    float et[T_SZ];
#pragma unroll
    for (int i = 0; i < T_SZ; ++i)
        et[i] = __expf(__ldg(trans + i * T_SZ + lane));

    const float* emb = em   + (size_t)b * S_SZ * T_SZ;
    const float* mb  = mask + (size_t)b * S_SZ;

    // exp-domain state: alpha_j = log(w_j) + E*ln2   (E warp-uniform)
    float w = __expf(__ldg(startT + lane) + __ldg(emb + lane));
    int   E = 0;

    // renorm scale lag pipeline: sc_a applied at the next renorm point,
    // sc_b in flight (computed from the most recent w)
    float sc_a, sc_b; int k_a, k_b;
    scale_from_max(w, sc_a, k_a);
    sc_b = sc_a;  k_b = k_a;

    // depth-8 prefetch ring: exp(emission) computed 8 steps ahead of use
    float eebuf[8], mbuf[8];
#pragma unroll
    for (int k = 0; k < 8; ++k) {
        eebuf[k] = __expf(__ldg(emb + (1 + k) * T_SZ + lane));
        mbuf[k]  = __ldg(mb + 1 + k);
    }

    // main loop: steps 1..1016 as 127 groups of 8 (compile-time ring slots)
    for (int g = 0; g < 127; ++g) {
        const int sb = 1 + g * 8;
        const bool pfl = (g < 126);   // last group: slot 7 would fetch s=1024
        STEP(0, true, false, sb + 0)
        STEP(1, true, false, sb + 1)
        STEP(2, true, false, sb + 2)
        STEP(3, true, true,  sb + 3)
        STEP(4, true, false, sb + 4)
        STEP(5, true, false, sb + 5)
        STEP(6, true, false, sb + 6)
        STEP(7, pfl,  true,  sb + 7)
    }
    // tail: steps 1017..1023 (slots 0..6), no prefetch, one renorm mid-tail
    STEP(0, false, false, 1017)
    STEP(1, false, false, 1018)
    STEP(2, false, false, 1019)
    STEP(3, false, true,  1020)
    STEP(4, false, false, 1021)
    STEP(5, false, false, 1022)
    STEP(6, false, false, 1023)

    // ---- partition_b = E*ln2 + log( sum_j w_j * exp(endT_j) ) ----
    float v = w * __expf(__ldg(endT + lane));
#pragma unroll
    for (int o = 16; o > 0; o >>= 1)
        v += __shfl_xor_sync(FULL, v, o);
    const float part = fmaf((float)E, LN2F, __logf(v));

    // ---- score_b: lanes stride over positions ----
    const int* tb = tags + (size_t)b * S_SZ;
    float sacc = 0.f, msum = 0.f;
#pragma unroll 4
    for (int s = lane; s < S_SZ; s += 32) {
        const float mm = __ldg(mb + s);
        msum += mm;
        if (s == 0) {
            const int t0 = __ldg(tb) & (T_SZ - 1);
            sacc += __ldg(startT + t0) + __ldg(emb + t0);
        } else {
            const int tc = __ldg(tb + s)     & (T_SZ - 1);
            const int tp = __ldg(tb + s - 1) & (T_SZ - 1);
            sacc += (__ldg(emb + s * T_SZ + tc) + __ldg(trans + tp * T_SZ + tc)) * mm;
        }
    }
#pragma unroll
    for (int o = 16; o > 0; o >>= 1) {
        sacc += __shfl_xor_sync(FULL, sacc, o);
        msum += __shfl_xor_sync(FULL, msum, o);
    }

    if (lane == 0) {
        int last = (int)msum - 1;
        last = last < 0 ? 0 : (last >= S_SZ ? S_SZ - 1 : last);
        const int tl = __ldg(tb + last) & (T_SZ - 1);
        g_res[b] = part - (sacc + __ldg(endT + tl));
    }

    // ---- fused final reduction: last block to finish sums all 512 ----
    __syncthreads();
    __threadfence();
    if (threadIdx.x == 0)
        s_ticket = atomicAdd(&g_cnt, 1u);
    __syncthreads();

    if (s_ticket == gridDim.x - 1) {
        const int t = threadIdx.x;
        red[t] = g_res[t] + g_res[t + 128] + g_res[t + 256] + g_res[t + 384];
        __syncthreads();
#pragma unroll
        for (int st = 64; st > 0; st >>= 1) {
            if (t < st) red[t] += red[t + st];
            __syncthreads();
        }
        if (t == 0) { out[0] = red[0]; g_cnt = 0; }
    }
}

extern "C" void kernel_launch(void* const* d_in, const int* in_sizes, int n_in,
                              void* d_out, int out_size)
{
    const float* em     = (const float*)d_in[0];
    const int*   tags   = (const int*)d_in[1];
    const float* mask   = (const float*)d_in[2];
    const float* trans  = (const float*)d_in[3];
    const float* startT = (const float*)d_in[4];
    const float* endT   = (const float*)d_in[5];
    float* out = (float*)d_out;

    (void)in_sizes; (void)n_in; (void)out_size;

    // 128 blocks x 128 threads = 512 warps = one warp per batch
    crf_kernel<<<B_SZ / 4, 128>>>(em, tags, mask, trans, startT, endT, out);
}